// round 12
// baseline (speedup 1.0000x reference)
#include <cuda_runtime.h>
#include <cuda_fp16.h>

#define S_TOT 2048
#define B_DIM 64
#define N_DIM 256
#define EPSV 0.01f
#define INV_EPS 100.0f
#define THRESH 0.1f
#define MAX_ITER 100
#define LOG_EPS 1e-8f
#define THREADS 512

// smem layout (float offsets); E0h occupies floats [0,8192) as half[16384].
#define O_EUWT  8192    // float4[64]: (eu0, wt0, eu1, wt1)
#define O_SPART 8448    // spartA float4[384] @8448, spartB float4[384] @9984
#define O_SNU   11520   // snu0 [256], snu1 [256]
#define O_SEV   12032   // sev0 [256], sev1 [256]
#define O_SU    12544   // 2 x 64
#define O_SLM   12672   // 2 x 64
#define O_SMU   12800   // 2 x 64
#define O_SRED  12928   // 2 x 32: [0..3]=mv partials, [8..15]=du partials,
                        //         [16..23]=u-max partials, [24]=m_v, [25]=m_u
#define O_RS    12992   // 64: row sums of fp16 E0
#define O_CMW   13056   // 16: per-warp cmin partials
#define SMEM_FLOATS 13072

#define MAX8(a) fmaxf(fmaxf(fmaxf((a)[0],(a)[1]),fmaxf((a)[2],(a)[3])), \
                      fmaxf(fmaxf((a)[4],(a)[5]),fmaxf((a)[6],(a)[7])))
#define SUM8(a) ((((a)[0]+(a)[1])+((a)[2]+(a)[3]))+(((a)[4]+(a)[5])+((a)[6]+(a)[7])))

// ---------------------------------------------------------------------------
// SINGLE kernel: each block builds its own fp16 E0 in shared directly from C
// (redundant deterministic cmin; exp on the idle MUFU pipe; row sums local).
// No global E0, no init kernel, no inter-block wait. Loop body identical to
// the 25.2us R11 kernel: v-pass -> break -> u-pass -> euwt, it0-u hoisted.
// ---------------------------------------------------------------------------
extern "C" __global__ void __launch_bounds__(THREADS, 3)
ot_main_kernel(const float* __restrict__ mu,
               const float* __restrict__ nu,
               const float* __restrict__ C,
               float* __restrict__ out) {
    extern __shared__ float sm[];
    __half* sE0h = reinterpret_cast<__half*>(sm);

    const int tid = threadIdx.x;
    const int h   = tid >> 8;          // sample slot
    const int col = tid & 255;
    const int l   = tid & 31;
    const int w   = tid >> 5;          // 0..15
    const int ws  = w & 7;
    const int qr  = tid >> 7;          // row-quarter (v mapping)
    const int cp  = tid & 127;         // col-pair

    float* snu0   = sm + O_SNU;
    float* snu1   = sm + O_SNU + 256;
    float* sev_h  = sm + O_SEV + (h << 8);
    float* su_h   = sm + O_SU  + (h << 6);
    float* slm_h  = sm + O_SLM + (h << 6);
    float* smu_h  = sm + O_SMU + (h << 6);
    float* sred0  = sm + O_SRED;
    float* sred1  = sm + O_SRED + 32;
    float* sred_h = sm + O_SRED + (h << 5);
    float4* spartA = reinterpret_cast<float4*>(sm + O_SPART);
    float4* spartB = spartA + 384;

    const int s0 = blockIdx.x * 2, s1 = s0 + 1, s_h = s0 + h;

    // ================= PROLOGUE =================
    // mu/nu loads (long-latency, independent of the C pipeline)
    sm[O_SNU + (h << 8) + col] = EPSV * __logf(nu[s_h * N_DIM + col] + LOG_EPS);
    if (col < B_DIM) {
        const float m = mu[s_h * B_DIM + col];
        smu_h[col] = m;
        slm_h[col] = __logf(m + LOG_EPS);
    }

    // ---- pass 1 over C: block-wide min (deterministic, same in all blocks) ----
    const float4* C4 = reinterpret_cast<const float4*>(C);
    float mn = 3.402823466e38f;
    #pragma unroll
    for (int k = 0; k < 8; k++) {
        const float4 c = C4[tid + THREADS * k];
        mn = fminf(mn, fminf(fminf(c.x, c.y), fminf(c.z, c.w)));
    }
    #pragma unroll
    for (int o = 16; o; o >>= 1)
        mn = fminf(mn, __shfl_xor_sync(0xFFFFFFFFu, mn, o));
    if (l == 0) sm[O_CMW + w] = mn;
    __syncthreads();                                        // Ba
    float cmin;
    {
        float t = sm[O_CMW];
        #pragma unroll
        for (int k = 1; k < 16; k++) t = fminf(t, sm[O_CMW + k]);
        cmin = t;
    }

    // ---- pass 2 over C (L1-hot): exp -> fp16 -> smem E0 ----
    #pragma unroll
    for (int k = 0; k < 8; k++) {
        const int idx = tid + THREADS * k;
        const float4 c = C4[idx];
        const __half2 h0 = __floats2half2_rn(__expf((cmin - c.x) * INV_EPS),
                                             __expf((cmin - c.y) * INV_EPS));
        const __half2 h1 = __floats2half2_rn(__expf((cmin - c.z) * INV_EPS),
                                             __expf((cmin - c.w) * INV_EPS));
        uint2 pk;
        pk.x = *reinterpret_cast<const unsigned*>(&h0);
        pk.y = *reinterpret_cast<const unsigned*>(&h1);
        reinterpret_cast<uint2*>(sE0h)[idx] = pk;
    }
    __syncthreads();                                        // Bb

    // ---- row sums of the fp16 E0 (same tree as the old init kernel) ----
    #pragma unroll
    for (int r = 0; r < 4; r++) {
        const int row = (w << 2) + r;
        const int4 hv = reinterpret_cast<const int4*>(sE0h + (row << 8))[l];
        const __half2* hp = reinterpret_cast<const __half2*>(&hv);
        const float2 f0 = __half22float2(hp[0]), f1 = __half22float2(hp[1]);
        const float2 f2 = __half22float2(hp[2]), f3 = __half22float2(hp[3]);
        float p = f0.x + f0.y + f1.x + f1.y + f2.x + f2.y + f3.x + f3.y;
        #pragma unroll
        for (int o = 16; o; o >>= 1)
            p += __shfl_xor_sync(0xFFFFFFFFu, p, o);
        if (l == 0) sm[O_RS + row] = p;
    }
    __syncthreads();                                        // Bc

    // ---- full it0 u-phase (u1 / err partials / euwt) ----
    if (col < B_DIM) {
        const float m  = smu_h[col];
        const float S  = sm[O_RS + col];
        const float u1 = EPSV * (slm_h[col] - __logf(S)) + cmin;
        su_h[col] = u1;
        float d = fabsf(u1);
        #pragma unroll
        for (int o = 16; o; o >>= 1)
            d += __shfl_xor_sync(0xFFFFFFFFu, d, o);
        if (l == 0) sred_h[8 + ws] = d;
        const float eu = (m + LOG_EPS) * (1.0f / S);
        float* qp = sm + O_EUWT + (col << 2);
        qp[2 * h]     = eu;
        qp[2 * h + 1] = eu * m;
    }
    if (l == 0 && ws >= 2) sred_h[8 + ws] = 0.0f;   // unused err partials
    if (tid == 0)   { sred0[24] = 0.0f; sred0[25] = cmin; }
    if (tid == 256) { sred1[24] = 0.0f; sred1[25] = cmin; }
    __syncthreads();                                        // P

    bool active0 = true, active1 = true;

    // ================= MAIN LOOP (v -> break -> u -> euwt) =================
    for (int it = 0; it < MAX_ITER; ++it) {
        const float err0 = SUM8(sred0 + 8);
        const float err1 = SUM8(sred1 + 8);
        const bool last0 = active0 && (err0 < THRESH || it == MAX_ITER - 1);
        const bool last1 = active1 && (err1 < THRESH || it == MAX_ITER - 1);
        const bool anyLast = last0 || last1;

        const __half2* cph = reinterpret_cast<const __half2*>(sE0h)
                           + (qr << 11) + cp;
        const float4* qw = reinterpret_cast<const float4*>(sm + O_EUWT) + (qr << 4);

        if (!anyLast) {
            // ===== LIGHT v-pass: av only, single-float4 exchange =====
            float av0a = 0, av0b = 0, av1a = 0, av1b = 0;
            #pragma unroll
            for (int i = 0; i < 16; i++) {
                const float2 cf = __half22float2(cph[i << 7]);
                const float4 q  = qw[i];
                av0a = fmaf(cf.x, q.x, av0a); av0b = fmaf(cf.y, q.x, av0b);
                av1a = fmaf(cf.x, q.z, av1a); av1b = fmaf(cf.y, q.z, av1b);
            }
            if (qr) spartA[((qr - 1) << 7) + cp] = make_float4(av0a, av0b, av1a, av1b);
            __syncthreads();                                    // B4
            if (qr == 0) {
                #pragma unroll
                for (int t = 0; t < 3; t++) {
                    const float4 pa = spartA[(t << 7) + cp];
                    av0a += pa.x; av0b += pa.y; av1a += pa.z; av1b += pa.w;
                }
                const float2 ln0 = *reinterpret_cast<const float2*>(snu0 + 2 * cp);
                const float2 ln1 = *reinterpret_cast<const float2*>(snu1 + 2 * cp);
                const float mue0 = sred0[25];
                const float mue1 = sred1[25];
                const float v0a = ln0.x - (mue0 - cmin) - EPSV * __logf(av0a);
                const float v0b = ln0.y - (mue0 - cmin) - EPSV * __logf(av0b);
                const float v1a = ln1.x - (mue1 - cmin) - EPSV * __logf(av1a);
                const float v1b = ln1.y - (mue1 - cmin) - EPSV * __logf(av1b);
                float m0 = fmaxf(v0a, v0b);
                float m1 = fmaxf(v1a, v1b);
                #pragma unroll
                for (int o = 16; o; o >>= 1) {
                    m0 = fmaxf(m0, __shfl_xor_sync(0xFFFFFFFFu, m0, o));
                    m1 = fmaxf(m1, __shfl_xor_sync(0xFFFFFFFFu, m1, o));
                }
                if (l == 0) { sred0[w] = m0; sred1[w] = m1; }   // w = 0..3
                asm volatile("bar.sync 1, 128;" ::: "memory");  // B5 (named)
                m0 = fmaxf(fmaxf(sred0[0], sred0[1]), fmaxf(sred0[2], sred0[3]));
                m1 = fmaxf(fmaxf(sred1[0], sred1[1]), fmaxf(sred1[2], sred1[3]));
                if (active0) {
                    *reinterpret_cast<float2*>(sm + O_SEV + 2 * cp)
                        = make_float2(__expf((v0a - m0) * INV_EPS),
                                      __expf((v0b - m0) * INV_EPS));
                    if (tid == 0) sred0[24] = m0;
                }
                if (active1) {
                    *reinterpret_cast<float2*>(sm + O_SEV + 256 + 2 * cp)
                        = make_float2(__expf((v1a - m1) * INV_EPS),
                                      __expf((v1b - m1) * INV_EPS));
                    if (tid == 0) sred1[24] = m1;
                }
            }
            __syncthreads();                                    // B6
        } else {
            // ===== FULL v-pass: av+ae, outputs written for last samples =====
            float av0a = 0, av0b = 0, ae0a = 0, ae0b = 0;
            float av1a = 0, av1b = 0, ae1a = 0, ae1b = 0;
            #pragma unroll
            for (int i = 0; i < 16; i++) {
                const float2 cf = __half22float2(cph[i << 7]);
                const float4 q  = qw[i];
                av0a = fmaf(cf.x, q.x, av0a); av0b = fmaf(cf.y, q.x, av0b);
                ae0a = fmaf(cf.x, q.y, ae0a); ae0b = fmaf(cf.y, q.y, ae0b);
                av1a = fmaf(cf.x, q.z, av1a); av1b = fmaf(cf.y, q.z, av1b);
                ae1a = fmaf(cf.x, q.w, ae1a); ae1b = fmaf(cf.y, q.w, ae1b);
            }
            if (qr) {
                spartA[((qr - 1) << 7) + cp] = make_float4(av0a, ae0a, av1a, ae1a);
                spartB[((qr - 1) << 7) + cp] = make_float4(av0b, ae0b, av1b, ae1b);
            }
            __syncthreads();                                    // B4
            if (qr == 0) {
                #pragma unroll
                for (int t = 0; t < 3; t++) {
                    const float4 pa = spartA[(t << 7) + cp];
                    const float4 pb = spartB[(t << 7) + cp];
                    av0a += pa.x; ae0a += pa.y; av1a += pa.z; ae1a += pa.w;
                    av0b += pb.x; ae0b += pb.y; av1b += pb.z; ae1b += pb.w;
                }
                const float2 ln0 = *reinterpret_cast<const float2*>(snu0 + 2 * cp);
                const float2 ln1 = *reinterpret_cast<const float2*>(snu1 + 2 * cp);
                const float mue0 = sred0[25];
                const float mue1 = sred1[25];
                const float v0a = ln0.x - (mue0 - cmin) - EPSV * __logf(av0a);
                const float v0b = ln0.y - (mue0 - cmin) - EPSV * __logf(av0b);
                const float v1a = ln1.x - (mue1 - cmin) - EPSV * __logf(av1a);
                const float v1b = ln1.y - (mue1 - cmin) - EPSV * __logf(av1b);
                float m0 = fmaxf(v0a, v0b);
                float m1 = fmaxf(v1a, v1b);
                #pragma unroll
                for (int o = 16; o; o >>= 1) {
                    m0 = fmaxf(m0, __shfl_xor_sync(0xFFFFFFFFu, m0, o));
                    m1 = fmaxf(m1, __shfl_xor_sync(0xFFFFFFFFu, m1, o));
                }
                if (l == 0) { sred0[w] = m0; sred1[w] = m1; }
                asm volatile("bar.sync 1, 128;" ::: "memory");  // B5 (named)
                m0 = fmaxf(fmaxf(sred0[0], sred0[1]), fmaxf(sred0[2], sred0[3]));
                m1 = fmaxf(fmaxf(sred1[0], sred1[1]), fmaxf(sred1[2], sred1[3]));
                if (active0) {
                    const float e0a = __expf((v0a - m0) * INV_EPS);
                    const float e0b = __expf((v0b - m0) * INV_EPS);
                    *reinterpret_cast<float2*>(sm + O_SEV + 2 * cp)
                        = make_float2(e0a, e0b);
                    if (tid == 0) sred0[24] = m0;
                    if (last0) {
                        const float sc = __expf((mue0 + m0 - cmin) * INV_EPS);
                        *reinterpret_cast<float2*>(out + s0 * N_DIM + 2 * cp)
                            = make_float2(sc * e0a * ae0a, sc * e0b * ae0b);
                    }
                }
                if (active1) {
                    const float e1a = __expf((v1a - m1) * INV_EPS);
                    const float e1b = __expf((v1b - m1) * INV_EPS);
                    *reinterpret_cast<float2*>(sm + O_SEV + 256 + 2 * cp)
                        = make_float2(e1a, e1b);
                    if (tid == 0) sred1[24] = m1;
                    if (last1) {
                        const float sc = __expf((mue1 + m1 - cmin) * INV_EPS);
                        *reinterpret_cast<float2*>(out + s1 * N_DIM + 2 * cp)
                            = make_float2(sc * e1a * ae1a, sc * e1b * ae1b);
                    }
                }
            }
            __syncthreads();                                    // B6
        }

        if (last0) active0 = false;
        if (last1) active1 = false;
        if (!active0 && !active1) break;

        // ---- u-pass for iteration it+1 (fused err/m_u partials) ----
        const bool act_h = h ? active1 : active0;
        if (act_h) {
            const float m_v_h = sred_h[24];
            const float4 evA = reinterpret_cast<const float4*>(sev_h)[2 * l];
            const float4 evB = reinterpret_cast<const float4*>(sev_h)[2 * l + 1];
            float myDu = 0.0f;
            float myU  = -3.402823466e38f;
            #pragma unroll
            for (int r = 0; r < 8; ++r) {
                const int row = (ws << 3) + r;
                const int4 hv = reinterpret_cast<const int4*>(sE0h + (row << 8))[l];
                const __half2* hp = reinterpret_cast<const __half2*>(&hv);
                const float2 f0 = __half22float2(hp[0]);
                const float2 f1 = __half22float2(hp[1]);
                const float2 f2 = __half22float2(hp[2]);
                const float2 f3 = __half22float2(hp[3]);
                float p = f0.x * evA.x + f0.y * evA.y + f1.x * evA.z + f1.y * evA.w
                        + f2.x * evB.x + f2.y * evB.y + f3.x * evB.z + f3.y * evB.w;
                #pragma unroll
                for (int o = 16; o; o >>= 1)
                    p += __shfl_xor_sync(0xFFFFFFFFu, p, o);
                if (l == r) {
                    const float unew = EPSV * slm_h[row] - (m_v_h - cmin)
                                     - EPSV * __logf(p);
                    myDu = fabsf(unew - su_h[row]);
                    myU  = unew;
                    su_h[row] = unew;
                }
            }
            #pragma unroll
            for (int o = 16; o; o >>= 1) {
                myDu += __shfl_xor_sync(0xFFFFFFFFu, myDu, o);
                myU   = fmaxf(myU, __shfl_xor_sync(0xFFFFFFFFu, myU, o));
            }
            if (l == 0) { sred_h[8 + ws] = myDu; sred_h[16 + ws] = myU; }
        }
        __syncthreads();                                        // B1

        // ---- euwt for iteration it+1 ----
        if (col < B_DIM && act_h) {
            const float mu_ = MAX8(sred_h + 16);
            const float eu = __expf((su_h[col] - mu_) * INV_EPS);
            float* qp = sm + O_EUWT + (col << 2);
            qp[2 * h]     = eu;
            qp[2 * h + 1] = eu * smu_h[col];
            if (col == 0) sred_h[25] = mu_;
        }
        __syncthreads();                                        // B3
    }
}

// ---------------------------------------------------------------------------
// Launch — single kernel, no globals, no init pass.
// ---------------------------------------------------------------------------
extern "C" void kernel_launch(void* const* d_in, const int* in_sizes, int n_in,
                              void* d_out, int out_size) {
    const float* mu = nullptr;
    const float* nu = nullptr;
    const float* C  = nullptr;
    for (int i = 0; i < n_in; ++i) {
        if (in_sizes[i] == S_TOT * B_DIM)      mu = (const float*)d_in[i];
        else if (in_sizes[i] == S_TOT * N_DIM) nu = (const float*)d_in[i];
        else if (in_sizes[i] == B_DIM * N_DIM) C  = (const float*)d_in[i];
    }
    float* out = (float*)d_out;

    const int smem_bytes = SMEM_FLOATS * sizeof(float);   // ~51.1 KB, 3 blk/SM
    cudaFuncSetAttribute(ot_main_kernel,
                         cudaFuncAttributeMaxDynamicSharedMemorySize, smem_bytes);

    ot_main_kernel<<<S_TOT / 2, THREADS, smem_bytes>>>(mu, nu, C, out);
}

// round 13
// speedup vs baseline: 1.2094x; 1.2094x over previous
#include <cuda_runtime.h>
#include <cuda_fp16.h>

#define S_TOT 2048
#define B_DIM 64
#define N_DIM 256
#define EPSV 0.01f
#define INV_EPS 100.0f
#define THRESH 0.1f
#define MAX_ITER 100
#define LOG_EPS 1e-8f
#define THREADS 512

// E0_ij = exp((Cmin - C_ij)/eps) in fp16; row sums (of fp16 values) in fp32.
__device__ __align__(16) __half g_E0h[B_DIM * N_DIM];
__device__ float g_logS[B_DIM];
__device__ float g_invS[B_DIM];
__device__ float g_Cmin;

// ---------------------------------------------------------------------------
// Init: 16 blocks x 256 threads. Triggers PDL completion at entry so the main
// grid launches concurrently. Every block redundantly computes cmin; block b
// builds rows 4b..4b+3 of E0h and their row sums.
// ---------------------------------------------------------------------------
__global__ void __launch_bounds__(256) ot_init_kernel(const float* __restrict__ C) {
    cudaTriggerProgrammaticLaunchCompletion();

    __shared__ float sred[9];
    const int tid = threadIdx.x, l = tid & 31, w = tid >> 5;

    float mn = 3.402823466e38f;
    const float4* C4 = reinterpret_cast<const float4*>(C);
    #pragma unroll
    for (int k = 0; k < 16; k++) {
        const float4 c = C4[tid + 256 * k];
        mn = fminf(mn, fminf(fminf(c.x, c.y), fminf(c.z, c.w)));
    }
    #pragma unroll
    for (int o = 16; o; o >>= 1)
        mn = fminf(mn, __shfl_xor_sync(0xFFFFFFFFu, mn, o));
    if (l == 0) sred[w] = mn;
    __syncthreads();
    if (tid == 0) {
        float t = sred[0];
        #pragma unroll
        for (int k = 1; k < 8; k++) t = fminf(t, sred[k]);
        sred[8] = t;
        if (blockIdx.x == 0) g_Cmin = t;
    }
    __syncthreads();
    const float cmin = sred[8];

    #pragma unroll
    for (int rr = 0; rr < 4; rr++) {
        const int row = blockIdx.x * 4 + rr;
        const float val = __expf((cmin - C[(row << 8) + tid]) * INV_EPS);
        const __half hv = __float2half_rn(val);
        g_E0h[(row << 8) + tid] = hv;
        float f = __half2float(hv);
        #pragma unroll
        for (int o = 16; o; o >>= 1)
            f += __shfl_xor_sync(0xFFFFFFFFu, f, o);
        __syncthreads();
        if (l == 0) sred[w] = f;
        __syncthreads();
        if (tid == 0) {
            float s = 0.0f;
            #pragma unroll
            for (int k = 0; k < 8; k++) s += sred[k];
            g_logS[row] = __logf(s);
            g_invS[row] = 1.0f / s;
        }
    }
}

// smem layout (float offsets); E0h occupies floats [0,8192) as half[16384].
#define O_EUWT  8192    // float4[64]: (eu0, wt0, eu1, wt1)
#define O_SPART 8448    // spartA float4[384] @8448, spartB float4[384] @9984
#define O_SNU   11520   // snu0 [256], snu1 [256]
#define O_SEV   12032   // sev0 [256], sev1 [256]
#define O_SU    12544   // 2 x 64
#define O_SLM   12672   // 2 x 64
#define O_SMU   12800   // 2 x 64
#define O_SRED  12928   // 2 x 32: [0..3]=mv partials, [8..15]=du partials,
                        //         [16..23]=u-max partials, [24]=m_v, [25]=m_u
#define SMEM_FLOATS 12992

#define MAX8(a) fmaxf(fmaxf(fmaxf((a)[0],(a)[1]),fmaxf((a)[2],(a)[3])), \
                      fmaxf(fmaxf((a)[4],(a)[5]),fmaxf((a)[6],(a)[7])))
#define SUM8(a) ((((a)[0]+(a)[1])+((a)[2]+(a)[3]))+(((a)[4]+(a)[5])+((a)[6]+(a)[7])))

// ---------------------------------------------------------------------------
// Main (R11 verbatim + PDL): 2 samples/block, 512 threads, fp16 E0 shared,
// 3 blocks/SM. Independent mu/nu LDGs issue BEFORE gridDependencySynchronize;
// everything touching g_* comes after. Loop: v -> break -> u -> euwt.
// ---------------------------------------------------------------------------
extern "C" __global__ void __launch_bounds__(THREADS, 3)
ot_main_kernel(const float* __restrict__ mu,
               const float* __restrict__ nu,
               float* __restrict__ out) {
    extern __shared__ float sm[];
    __half* sE0h = reinterpret_cast<__half*>(sm);

    const int tid = threadIdx.x;
    const int h   = tid >> 8;          // sample slot
    const int col = tid & 255;
    const int l   = tid & 31;
    const int w   = tid >> 5;          // 0..15
    const int ws  = w & 7;
    const int qr  = tid >> 7;          // row-quarter (v mapping)
    const int cp  = tid & 127;         // col-pair

    float* snu0   = sm + O_SNU;
    float* snu1   = sm + O_SNU + 256;
    float* sev_h  = sm + O_SEV + (h << 8);
    float* su_h   = sm + O_SU  + (h << 6);
    float* slm_h  = sm + O_SLM + (h << 6);
    float* smu_h  = sm + O_SMU + (h << 6);
    float* sred0  = sm + O_SRED;
    float* sred1  = sm + O_SRED + 32;
    float* sred_h = sm + O_SRED + (h << 5);
    float4* spartA = reinterpret_cast<float4*>(sm + O_SPART);
    float4* spartB = spartA + 384;

    const int s0 = blockIdx.x * 2, s1 = s0 + 1, s_h = s0 + h;

    // ---- independent prologue loads (overlap the init kernel via PDL) ----
    const float nuv = nu[s_h * N_DIM + col];
    float muv = 0.0f;
    if (col < B_DIM) muv = mu[s_h * B_DIM + col];

    cudaGridDependencySynchronize();   // init's E0h/logS/invS/cmin now visible

    const float cmin = g_Cmin;

    // ================= PROLOGUE (one barrier) =================
    {
        const uint4* g4 = reinterpret_cast<const uint4*>(g_E0h);
        uint4* s4 = reinterpret_cast<uint4*>(sE0h);
        #pragma unroll
        for (int k = 0; k < 4; k++)
            s4[tid + THREADS * k] = g4[tid + THREADS * k];
    }
    sm[O_SNU + (h << 8) + col] = EPSV * __logf(nuv + LOG_EPS);
    if (col < B_DIM) {
        const float lm = __logf(muv + LOG_EPS);
        smu_h[col] = muv;
        slm_h[col] = lm;
        const float u1 = EPSV * (lm - g_logS[col]) + cmin;
        su_h[col] = u1;
        float d = fabsf(u1);
        #pragma unroll
        for (int o = 16; o; o >>= 1)
            d += __shfl_xor_sync(0xFFFFFFFFu, d, o);
        if (l == 0) sred_h[8 + ws] = d;
        const float eu = (muv + LOG_EPS) * g_invS[col];
        float* qp = sm + O_EUWT + (col << 2);
        qp[2 * h]     = eu;
        qp[2 * h + 1] = eu * muv;
    }
    if (l == 0 && ws >= 2) sred_h[8 + ws] = 0.0f;   // unused err partials
    if (tid == 0)   { sred0[24] = 0.0f; sred0[25] = cmin; }
    if (tid == 256) { sred1[24] = 0.0f; sred1[25] = cmin; }
    __syncthreads();                                        // P

    bool active0 = true, active1 = true;

    // ================= MAIN LOOP (v -> break -> u -> euwt) =================
    for (int it = 0; it < MAX_ITER; ++it) {
        const float err0 = SUM8(sred0 + 8);
        const float err1 = SUM8(sred1 + 8);
        const bool last0 = active0 && (err0 < THRESH || it == MAX_ITER - 1);
        const bool last1 = active1 && (err1 < THRESH || it == MAX_ITER - 1);
        const bool anyLast = last0 || last1;

        const __half2* cph = reinterpret_cast<const __half2*>(sE0h)
                           + (qr << 11) + cp;
        const float4* qw = reinterpret_cast<const float4*>(sm + O_EUWT) + (qr << 4);

        if (!anyLast) {
            // ===== LIGHT v-pass: av only, single-float4 exchange =====
            float av0a = 0, av0b = 0, av1a = 0, av1b = 0;
            #pragma unroll
            for (int i = 0; i < 16; i++) {
                const float2 cf = __half22float2(cph[i << 7]);
                const float4 q  = qw[i];
                av0a = fmaf(cf.x, q.x, av0a); av0b = fmaf(cf.y, q.x, av0b);
                av1a = fmaf(cf.x, q.z, av1a); av1b = fmaf(cf.y, q.z, av1b);
            }
            if (qr) spartA[((qr - 1) << 7) + cp] = make_float4(av0a, av0b, av1a, av1b);
            __syncthreads();                                    // B4
            if (qr == 0) {
                #pragma unroll
                for (int t = 0; t < 3; t++) {
                    const float4 pa = spartA[(t << 7) + cp];
                    av0a += pa.x; av0b += pa.y; av1a += pa.z; av1b += pa.w;
                }
                const float2 ln0 = *reinterpret_cast<const float2*>(snu0 + 2 * cp);
                const float2 ln1 = *reinterpret_cast<const float2*>(snu1 + 2 * cp);
                const float mue0 = sred0[25];
                const float mue1 = sred1[25];
                const float v0a = ln0.x - (mue0 - cmin) - EPSV * __logf(av0a);
                const float v0b = ln0.y - (mue0 - cmin) - EPSV * __logf(av0b);
                const float v1a = ln1.x - (mue1 - cmin) - EPSV * __logf(av1a);
                const float v1b = ln1.y - (mue1 - cmin) - EPSV * __logf(av1b);
                float m0 = fmaxf(v0a, v0b);
                float m1 = fmaxf(v1a, v1b);
                #pragma unroll
                for (int o = 16; o; o >>= 1) {
                    m0 = fmaxf(m0, __shfl_xor_sync(0xFFFFFFFFu, m0, o));
                    m1 = fmaxf(m1, __shfl_xor_sync(0xFFFFFFFFu, m1, o));
                }
                if (l == 0) { sred0[w] = m0; sred1[w] = m1; }   // w = 0..3
                asm volatile("bar.sync 1, 128;" ::: "memory");  // B5 (named)
                m0 = fmaxf(fmaxf(sred0[0], sred0[1]), fmaxf(sred0[2], sred0[3]));
                m1 = fmaxf(fmaxf(sred1[0], sred1[1]), fmaxf(sred1[2], sred1[3]));
                if (active0) {
                    *reinterpret_cast<float2*>(sm + O_SEV + 2 * cp)
                        = make_float2(__expf((v0a - m0) * INV_EPS),
                                      __expf((v0b - m0) * INV_EPS));
                    if (tid == 0) sred0[24] = m0;
                }
                if (active1) {
                    *reinterpret_cast<float2*>(sm + O_SEV + 256 + 2 * cp)
                        = make_float2(__expf((v1a - m1) * INV_EPS),
                                      __expf((v1b - m1) * INV_EPS));
                    if (tid == 0) sred1[24] = m1;
                }
            }
            __syncthreads();                                    // B6
        } else {
            // ===== FULL v-pass: av+ae, outputs written for last samples =====
            float av0a = 0, av0b = 0, ae0a = 0, ae0b = 0;
            float av1a = 0, av1b = 0, ae1a = 0, ae1b = 0;
            #pragma unroll
            for (int i = 0; i < 16; i++) {
                const float2 cf = __half22float2(cph[i << 7]);
                const float4 q  = qw[i];
                av0a = fmaf(cf.x, q.x, av0a); av0b = fmaf(cf.y, q.x, av0b);
                ae0a = fmaf(cf.x, q.y, ae0a); ae0b = fmaf(cf.y, q.y, ae0b);
                av1a = fmaf(cf.x, q.z, av1a); av1b = fmaf(cf.y, q.z, av1b);
                ae1a = fmaf(cf.x, q.w, ae1a); ae1b = fmaf(cf.y, q.w, ae1b);
            }
            if (qr) {
                spartA[((qr - 1) << 7) + cp] = make_float4(av0a, ae0a, av1a, ae1a);
                spartB[((qr - 1) << 7) + cp] = make_float4(av0b, ae0b, av1b, ae1b);
            }
            __syncthreads();                                    // B4
            if (qr == 0) {
                #pragma unroll
                for (int t = 0; t < 3; t++) {
                    const float4 pa = spartA[(t << 7) + cp];
                    const float4 pb = spartB[(t << 7) + cp];
                    av0a += pa.x; ae0a += pa.y; av1a += pa.z; ae1a += pa.w;
                    av0b += pb.x; ae0b += pb.y; av1b += pb.z; ae1b += pb.w;
                }
                const float2 ln0 = *reinterpret_cast<const float2*>(snu0 + 2 * cp);
                const float2 ln1 = *reinterpret_cast<const float2*>(snu1 + 2 * cp);
                const float mue0 = sred0[25];
                const float mue1 = sred1[25];
                const float v0a = ln0.x - (mue0 - cmin) - EPSV * __logf(av0a);
                const float v0b = ln0.y - (mue0 - cmin) - EPSV * __logf(av0b);
                const float v1a = ln1.x - (mue1 - cmin) - EPSV * __logf(av1a);
                const float v1b = ln1.y - (mue1 - cmin) - EPSV * __logf(av1b);
                float m0 = fmaxf(v0a, v0b);
                float m1 = fmaxf(v1a, v1b);
                #pragma unroll
                for (int o = 16; o; o >>= 1) {
                    m0 = fmaxf(m0, __shfl_xor_sync(0xFFFFFFFFu, m0, o));
                    m1 = fmaxf(m1, __shfl_xor_sync(0xFFFFFFFFu, m1, o));
                }
                if (l == 0) { sred0[w] = m0; sred1[w] = m1; }
                asm volatile("bar.sync 1, 128;" ::: "memory");  // B5 (named)
                m0 = fmaxf(fmaxf(sred0[0], sred0[1]), fmaxf(sred0[2], sred0[3]));
                m1 = fmaxf(fmaxf(sred1[0], sred1[1]), fmaxf(sred1[2], sred1[3]));
                if (active0) {
                    const float e0a = __expf((v0a - m0) * INV_EPS);
                    const float e0b = __expf((v0b - m0) * INV_EPS);
                    *reinterpret_cast<float2*>(sm + O_SEV + 2 * cp)
                        = make_float2(e0a, e0b);
                    if (tid == 0) sred0[24] = m0;
                    if (last0) {
                        const float sc = __expf((mue0 + m0 - cmin) * INV_EPS);
                        *reinterpret_cast<float2*>(out + s0 * N_DIM + 2 * cp)
                            = make_float2(sc * e0a * ae0a, sc * e0b * ae0b);
                    }
                }
                if (active1) {
                    const float e1a = __expf((v1a - m1) * INV_EPS);
                    const float e1b = __expf((v1b - m1) * INV_EPS);
                    *reinterpret_cast<float2*>(sm + O_SEV + 256 + 2 * cp)
                        = make_float2(e1a, e1b);
                    if (tid == 0) sred1[24] = m1;
                    if (last1) {
                        const float sc = __expf((mue1 + m1 - cmin) * INV_EPS);
                        *reinterpret_cast<float2*>(out + s1 * N_DIM + 2 * cp)
                            = make_float2(sc * e1a * ae1a, sc * e1b * ae1b);
                    }
                }
            }
            __syncthreads();                                    // B6
        }

        if (last0) active0 = false;
        if (last1) active1 = false;
        if (!active0 && !active1) break;

        // ---- u-pass for iteration it+1 (fused err/m_u partials) ----
        const bool act_h = h ? active1 : active0;
        if (act_h) {
            const float m_v_h = sred_h[24];
            const float4 evA = reinterpret_cast<const float4*>(sev_h)[2 * l];
            const float4 evB = reinterpret_cast<const float4*>(sev_h)[2 * l + 1];
            float myDu = 0.0f;
            float myU  = -3.402823466e38f;
            #pragma unroll
            for (int r = 0; r < 8; ++r) {
                const int row = (ws << 3) + r;
                const int4 hv = reinterpret_cast<const int4*>(sE0h + (row << 8))[l];
                const __half2* hp = reinterpret_cast<const __half2*>(&hv);
                const float2 f0 = __half22float2(hp[0]);
                const float2 f1 = __half22float2(hp[1]);
                const float2 f2 = __half22float2(hp[2]);
                const float2 f3 = __half22float2(hp[3]);
                float p = f0.x * evA.x + f0.y * evA.y + f1.x * evA.z + f1.y * evA.w
                        + f2.x * evB.x + f2.y * evB.y + f3.x * evB.z + f3.y * evB.w;
                #pragma unroll
                for (int o = 16; o; o >>= 1)
                    p += __shfl_xor_sync(0xFFFFFFFFu, p, o);
                if (l == r) {
                    const float unew = EPSV * slm_h[row] - (m_v_h - cmin)
                                     - EPSV * __logf(p);
                    myDu = fabsf(unew - su_h[row]);
                    myU  = unew;
                    su_h[row] = unew;
                }
            }
            #pragma unroll
            for (int o = 16; o; o >>= 1) {
                myDu += __shfl_xor_sync(0xFFFFFFFFu, myDu, o);
                myU   = fmaxf(myU, __shfl_xor_sync(0xFFFFFFFFu, myU, o));
            }
            if (l == 0) { sred_h[8 + ws] = myDu; sred_h[16 + ws] = myU; }
        }
        __syncthreads();                                        // B1

        // ---- euwt for iteration it+1 ----
        if (col < B_DIM && act_h) {
            const float mu_ = MAX8(sred_h + 16);
            const float eu = __expf((su_h[col] - mu_) * INV_EPS);
            float* qp = sm + O_EUWT + (col << 2);
            qp[2 * h]     = eu;
            qp[2 * h + 1] = eu * smu_h[col];
            if (col == 0) sred_h[25] = mu_;
        }
        __syncthreads();                                        // B3
    }
}

// ---------------------------------------------------------------------------
// Launch: init normally; main with PDL (programmatic stream serialization).
// ---------------------------------------------------------------------------
extern "C" void kernel_launch(void* const* d_in, const int* in_sizes, int n_in,
                              void* d_out, int out_size) {
    const float* mu = nullptr;
    const float* nu = nullptr;
    const float* C  = nullptr;
    for (int i = 0; i < n_in; ++i) {
        if (in_sizes[i] == S_TOT * B_DIM)      mu = (const float*)d_in[i];
        else if (in_sizes[i] == S_TOT * N_DIM) nu = (const float*)d_in[i];
        else if (in_sizes[i] == B_DIM * N_DIM) C  = (const float*)d_in[i];
    }
    float* out = (float*)d_out;

    const int smem_bytes = SMEM_FLOATS * sizeof(float);   // ~50.8 KB, 3 blk/SM
    cudaFuncSetAttribute(ot_main_kernel,
                         cudaFuncAttributeMaxDynamicSharedMemorySize, smem_bytes);

    ot_init_kernel<<<16, 256>>>(C);

    cudaLaunchConfig_t cfg = {};
    cfg.gridDim  = dim3(S_TOT / 2, 1, 1);
    cfg.blockDim = dim3(THREADS, 1, 1);
    cfg.dynamicSmemBytes = smem_bytes;
    cfg.stream = 0;
    cudaLaunchAttribute attr[1];
    attr[0].id = cudaLaunchAttributeProgrammaticStreamSerialization;
    attr[0].val.programmaticStreamSerializationAllowed = 1;
    cfg.attrs = attr;
    cfg.numAttrs = 1;
    cudaLaunchKernelEx(&cfg, ot_main_kernel, mu, nu, out);
}

// round 14
// speedup vs baseline: 1.3007x; 1.0755x over previous
#include <cuda_runtime.h>
#include <cuda_fp16.h>

#define S_TOT 2048
#define B_DIM 64
#define N_DIM 256
#define EPSV 0.01f
#define INV_EPS 100.0f
#define THRESH 0.1f
#define MAX_ITER 100
#define LOG_EPS 1e-8f
#define THREADS 512

// E0_ij = exp((Cmin - C_ij)/eps) in fp16; row sums (of fp16 values) in fp32.
__device__ __align__(16) __half g_E0h[B_DIM * N_DIM];
__device__ float g_logS[B_DIM];
__device__ float g_invS[B_DIM];
__device__ float g_Cmin;

// ---------------------------------------------------------------------------
// Init: 16 blocks x 256 threads, PDL trigger at entry.
// ---------------------------------------------------------------------------
__global__ void __launch_bounds__(256) ot_init_kernel(const float* __restrict__ C) {
    cudaTriggerProgrammaticLaunchCompletion();

    __shared__ float sred[9];
    const int tid = threadIdx.x, l = tid & 31, w = tid >> 5;

    float mn = 3.402823466e38f;
    const float4* C4 = reinterpret_cast<const float4*>(C);
    #pragma unroll
    for (int k = 0; k < 16; k++) {
        const float4 c = C4[tid + 256 * k];
        mn = fminf(mn, fminf(fminf(c.x, c.y), fminf(c.z, c.w)));
    }
    #pragma unroll
    for (int o = 16; o; o >>= 1)
        mn = fminf(mn, __shfl_xor_sync(0xFFFFFFFFu, mn, o));
    if (l == 0) sred[w] = mn;
    __syncthreads();
    if (tid == 0) {
        float t = sred[0];
        #pragma unroll
        for (int k = 1; k < 8; k++) t = fminf(t, sred[k]);
        sred[8] = t;
        if (blockIdx.x == 0) g_Cmin = t;
    }
    __syncthreads();
    const float cmin = sred[8];

    #pragma unroll
    for (int rr = 0; rr < 4; rr++) {
        const int row = blockIdx.x * 4 + rr;
        const float val = __expf((cmin - C[(row << 8) + tid]) * INV_EPS);
        const __half hv = __float2half_rn(val);
        g_E0h[(row << 8) + tid] = hv;
        float f = __half2float(hv);
        #pragma unroll
        for (int o = 16; o; o >>= 1)
            f += __shfl_xor_sync(0xFFFFFFFFu, f, o);
        __syncthreads();
        if (l == 0) sred[w] = f;
        __syncthreads();
        if (tid == 0) {
            float s = 0.0f;
            #pragma unroll
            for (int k = 0; k < 8; k++) s += sred[k];
            g_logS[row] = __logf(s);
            g_invS[row] = 1.0f / s;
        }
    }
}

// smem layout (float offsets); E0h occupies floats [0,8192) as half[16384].
#define O_EUWT  8192    // float4[64]: (eu0, wt0, eu1, wt1)
#define O_SPART 8448    // spartA float4[384] @8448, spartB float4[384] @9984
#define O_SNU   11520   // Knu0 [256], Knu1 [256]   (Knu = (nu+1e-8)*e^(-cmin/eps))
#define O_SEV   12032   // sev0 [256], sev1 [256]   (ev = Knu/av)
#define O_SU    12544   // 2 x 64  (log-domain u, for du/err only)
#define O_SLM   12672   // 2 x 64  log(mu+1e-8)
#define O_SMU   12800   // 2 x 64  mu
#define O_SKMU  12928   // 2 x 64  (mu+1e-8)*e^(-cmin/eps)
#define O_SRED  13056   // 2 x 16: [8..15] du partials
#define SMEM_FLOATS 13088

#define SUM8(a) ((((a)[0]+(a)[1])+((a)[2]+(a)[3]))+(((a)[4]+(a)[5])+((a)[6]+(a)[7])))

// ---------------------------------------------------------------------------
// Main: multiplicative Sinkhorn with fixed shift = cmin. eu = Kmu/p,
// ev = Knu/av, out = scale*ev*ae — no max reductions, no exp/log in the loop
// except logf(p) for the reference err. 3 barriers per iteration.
// ---------------------------------------------------------------------------
extern "C" __global__ void __launch_bounds__(THREADS, 3)
ot_main_kernel(const float* __restrict__ mu,
               const float* __restrict__ nu,
               float* __restrict__ out) {
    extern __shared__ float sm[];
    __half* sE0h = reinterpret_cast<__half*>(sm);

    const int tid = threadIdx.x;
    const int h   = tid >> 8;          // sample slot
    const int col = tid & 255;
    const int l   = tid & 31;
    const int w   = tid >> 5;          // 0..15
    const int ws  = w & 7;
    const int qr  = tid >> 7;          // row-quarter (v mapping)
    const int cp  = tid & 127;         // col-pair

    float* snu0   = sm + O_SNU;
    float* snu1   = sm + O_SNU + 256;
    float* sev_h  = sm + O_SEV + (h << 8);
    float* su_h   = sm + O_SU  + (h << 6);
    float* slm_h  = sm + O_SLM + (h << 6);
    float* smu_h  = sm + O_SMU + (h << 6);
    float* skmu_h = sm + O_SKMU + (h << 6);
    float* sred0  = sm + O_SRED;
    float* sred1  = sm + O_SRED + 16;
    float* sred_h = sm + O_SRED + (h << 4);
    float4* spartA = reinterpret_cast<float4*>(sm + O_SPART);
    float4* spartB = spartA + 384;

    const int s0 = blockIdx.x * 2, s1 = s0 + 1, s_h = s0 + h;

    // ---- independent prologue loads (overlap init via PDL) ----
    const float nuv = nu[s_h * N_DIM + col];
    float muv = 0.0f;
    if (col < B_DIM) muv = mu[s_h * B_DIM + col];

    cudaGridDependencySynchronize();

    const float cmin  = g_Cmin;
    const float en50  = __expf(-cmin * INV_EPS);   // e^(-cmin/eps)
    const float scale = __expf( cmin * INV_EPS);   // e^(+cmin/eps)

    // ================= PROLOGUE (one barrier) =================
    {
        const uint4* g4 = reinterpret_cast<const uint4*>(g_E0h);
        uint4* s4 = reinterpret_cast<uint4*>(sE0h);
        #pragma unroll
        for (int k = 0; k < 4; k++)
            s4[tid + THREADS * k] = g4[tid + THREADS * k];
    }
    sm[O_SNU + (h << 8) + col] = (nuv + LOG_EPS) * en50;   // Knu
    if (col < B_DIM) {
        const float mt = muv + LOG_EPS;
        const float lm = __logf(mt);
        smu_h[col]  = muv;
        slm_h[col]  = lm;
        skmu_h[col] = mt * en50;
        const float u1 = EPSV * (lm - g_logS[col]) + cmin;
        su_h[col] = u1;
        float d = fabsf(u1);
        #pragma unroll
        for (int o = 16; o; o >>= 1)
            d += __shfl_xor_sync(0xFFFFFFFFu, d, o);
        if (l == 0) sred_h[8 + ws] = d;
        const float eu = mt * g_invS[col];     // = Kmu / (S*en50), exact same value
        float* qp = sm + O_EUWT + (col << 2);
        qp[2 * h]     = eu;
        qp[2 * h + 1] = eu * muv;
    }
    if (l == 0 && ws >= 2) sred_h[8 + ws] = 0.0f;
    __syncthreads();                                        // P

    bool active0 = true, active1 = true;

    // ================= MAIN LOOP (v -> break -> u) =================
    for (int it = 0; it < MAX_ITER; ++it) {
        const float err0 = SUM8(sred0 + 8);
        const float err1 = SUM8(sred1 + 8);
        const bool last0 = active0 && (err0 < THRESH || it == MAX_ITER - 1);
        const bool last1 = active1 && (err1 < THRESH || it == MAX_ITER - 1);
        const bool anyLast = last0 || last1;

        const __half2* cph = reinterpret_cast<const __half2*>(sE0h)
                           + (qr << 11) + cp;
        const float4* qw = reinterpret_cast<const float4*>(sm + O_EUWT) + (qr << 4);

        if (!anyLast) {
            // ===== LIGHT v-pass: av only =====
            float av0a = 0, av0b = 0, av1a = 0, av1b = 0;
            #pragma unroll
            for (int i = 0; i < 16; i++) {
                const float2 cf = __half22float2(cph[i << 7]);
                const float4 q  = qw[i];
                av0a = fmaf(cf.x, q.x, av0a); av0b = fmaf(cf.y, q.x, av0b);
                av1a = fmaf(cf.x, q.z, av1a); av1b = fmaf(cf.y, q.z, av1b);
            }
            if (qr) spartA[((qr - 1) << 7) + cp] = make_float4(av0a, av0b, av1a, av1b);
            __syncthreads();                                    // B4
            if (qr == 0) {
                #pragma unroll
                for (int t = 0; t < 3; t++) {
                    const float4 pa = spartA[(t << 7) + cp];
                    av0a += pa.x; av0b += pa.y; av1a += pa.z; av1b += pa.w;
                }
                const float2 kn0 = *reinterpret_cast<const float2*>(snu0 + 2 * cp);
                const float2 kn1 = *reinterpret_cast<const float2*>(snu1 + 2 * cp);
                if (active0)
                    *reinterpret_cast<float2*>(sm + O_SEV + 2 * cp)
                        = make_float2(__fdividef(kn0.x, av0a),
                                      __fdividef(kn0.y, av0b));
                if (active1)
                    *reinterpret_cast<float2*>(sm + O_SEV + 256 + 2 * cp)
                        = make_float2(__fdividef(kn1.x, av1a),
                                      __fdividef(kn1.y, av1b));
            }
            __syncthreads();                                    // B6
        } else {
            // ===== FULL v-pass: av+ae, outputs for finishing samples =====
            float av0a = 0, av0b = 0, ae0a = 0, ae0b = 0;
            float av1a = 0, av1b = 0, ae1a = 0, ae1b = 0;
            #pragma unroll
            for (int i = 0; i < 16; i++) {
                const float2 cf = __half22float2(cph[i << 7]);
                const float4 q  = qw[i];
                av0a = fmaf(cf.x, q.x, av0a); av0b = fmaf(cf.y, q.x, av0b);
                ae0a = fmaf(cf.x, q.y, ae0a); ae0b = fmaf(cf.y, q.y, ae0b);
                av1a = fmaf(cf.x, q.z, av1a); av1b = fmaf(cf.y, q.z, av1b);
                ae1a = fmaf(cf.x, q.w, ae1a); ae1b = fmaf(cf.y, q.w, ae1b);
            }
            if (qr) {
                spartA[((qr - 1) << 7) + cp] = make_float4(av0a, ae0a, av1a, ae1a);
                spartB[((qr - 1) << 7) + cp] = make_float4(av0b, ae0b, av1b, ae1b);
            }
            __syncthreads();                                    // B4
            if (qr == 0) {
                #pragma unroll
                for (int t = 0; t < 3; t++) {
                    const float4 pa = spartA[(t << 7) + cp];
                    const float4 pb = spartB[(t << 7) + cp];
                    av0a += pa.x; ae0a += pa.y; av1a += pa.z; ae1a += pa.w;
                    av0b += pb.x; ae0b += pb.y; av1b += pb.z; ae1b += pb.w;
                }
                const float2 kn0 = *reinterpret_cast<const float2*>(snu0 + 2 * cp);
                const float2 kn1 = *reinterpret_cast<const float2*>(snu1 + 2 * cp);
                if (active0) {
                    const float e0a = __fdividef(kn0.x, av0a);
                    const float e0b = __fdividef(kn0.y, av0b);
                    *reinterpret_cast<float2*>(sm + O_SEV + 2 * cp)
                        = make_float2(e0a, e0b);
                    if (last0)
                        *reinterpret_cast<float2*>(out + s0 * N_DIM + 2 * cp)
                            = make_float2(scale * e0a * ae0a, scale * e0b * ae0b);
                }
                if (active1) {
                    const float e1a = __fdividef(kn1.x, av1a);
                    const float e1b = __fdividef(kn1.y, av1b);
                    *reinterpret_cast<float2*>(sm + O_SEV + 256 + 2 * cp)
                        = make_float2(e1a, e1b);
                    if (last1)
                        *reinterpret_cast<float2*>(out + s1 * N_DIM + 2 * cp)
                            = make_float2(scale * e1a * ae1a, scale * e1b * ae1b);
                }
            }
            __syncthreads();                                    // B6
        }

        if (last0) active0 = false;
        if (last1) active1 = false;
        if (!active0 && !active1) break;

        // ---- u-pass for it+1: dot + du/err + inline eu/wt (no extra barrier) ----
        const bool act_h = h ? active1 : active0;
        if (act_h) {
            const float4 evA = reinterpret_cast<const float4*>(sev_h)[2 * l];
            const float4 evB = reinterpret_cast<const float4*>(sev_h)[2 * l + 1];
            float myDu = 0.0f;
            #pragma unroll
            for (int r = 0; r < 8; ++r) {
                const int row = (ws << 3) + r;
                const int4 hv = reinterpret_cast<const int4*>(sE0h + (row << 8))[l];
                const __half2* hp = reinterpret_cast<const __half2*>(&hv);
                const float2 f0 = __half22float2(hp[0]);
                const float2 f1 = __half22float2(hp[1]);
                const float2 f2 = __half22float2(hp[2]);
                const float2 f3 = __half22float2(hp[3]);
                float p = f0.x * evA.x + f0.y * evA.y + f1.x * evA.z + f1.y * evA.w
                        + f2.x * evB.x + f2.y * evB.y + f3.x * evB.z + f3.y * evB.w;
                #pragma unroll
                for (int o = 16; o; o >>= 1)
                    p += __shfl_xor_sync(0xFFFFFFFFu, p, o);
                if (l == r) {
                    const float unew = EPSV * (slm_h[row] - __logf(p));
                    myDu = fabsf(unew - su_h[row]);
                    su_h[row] = unew;
                    const float eu = __fdividef(skmu_h[row], p);
                    float* qp = sm + O_EUWT + (row << 2);
                    qp[2 * h]     = eu;
                    qp[2 * h + 1] = eu * smu_h[row];
                }
            }
            #pragma unroll
            for (int o = 16; o; o >>= 1)
                myDu += __shfl_xor_sync(0xFFFFFFFFu, myDu, o);
            if (l == 0) sred_h[8 + ws] = myDu;
        }
        __syncthreads();                                        // B1
    }
}

// ---------------------------------------------------------------------------
// Launch: init normally; main with PDL.
// ---------------------------------------------------------------------------
extern "C" void kernel_launch(void* const* d_in, const int* in_sizes, int n_in,
                              void* d_out, int out_size) {
    const float* mu = nullptr;
    const float* nu = nullptr;
    const float* C  = nullptr;
    for (int i = 0; i < n_in; ++i) {
        if (in_sizes[i] == S_TOT * B_DIM)      mu = (const float*)d_in[i];
        else if (in_sizes[i] == S_TOT * N_DIM) nu = (const float*)d_in[i];
        else if (in_sizes[i] == B_DIM * N_DIM) C  = (const float*)d_in[i];
    }
    float* out = (float*)d_out;

    const int smem_bytes = SMEM_FLOATS * sizeof(float);   // ~51.1 KB, 3 blk/SM
    cudaFuncSetAttribute(ot_main_kernel,
                         cudaFuncAttributeMaxDynamicSharedMemorySize, smem_bytes);

    ot_init_kernel<<<16, 256>>>(C);

    cudaLaunchConfig_t cfg = {};
    cfg.gridDim  = dim3(S_TOT / 2, 1, 1);
    cfg.blockDim = dim3(THREADS, 1, 1);
    cfg.dynamicSmemBytes = smem_bytes;
    cfg.stream = 0;
    cudaLaunchAttribute attr[1];
    attr[0].id = cudaLaunchAttributeProgrammaticStreamSerialization;
    attr[0].val.programmaticStreamSerializationAllowed = 1;
    cfg.attrs = attr;
    cfg.numAttrs = 1;
    cudaLaunchKernelEx(&cfg, ot_main_kernel, mu, nu, out);
}

// round 15
// speedup vs baseline: 1.4232x; 1.0942x over previous
#include <cuda_runtime.h>
#include <cuda_fp16.h>

#define S_TOT 2048
#define B_DIM 64
#define N_DIM 256
#define EPSV 0.01f
#define INV_EPS 100.0f
#define THRESH 0.1f
#define MAX_ITER 100
#define LOG_EPS 1e-8f
#define THREADS 512

// E0_ij = exp((Cmin - C_ij)/eps) in fp16; row sums (of fp16 values) in fp32.
__device__ __align__(16) __half g_E0h[B_DIM * N_DIM];
__device__ float g_logS[B_DIM];
__device__ float g_invS[B_DIM];
__device__ float g_Cmin;

// ---------------------------------------------------------------------------
// Init: 16 blocks x 256 threads, PDL trigger at entry.
// ---------------------------------------------------------------------------
__global__ void __launch_bounds__(256) ot_init_kernel(const float* __restrict__ C) {
    cudaTriggerProgrammaticLaunchCompletion();

    __shared__ float sred[9];
    const int tid = threadIdx.x, l = tid & 31, w = tid >> 5;

    float mn = 3.402823466e38f;
    const float4* C4 = reinterpret_cast<const float4*>(C);
    #pragma unroll
    for (int k = 0; k < 16; k++) {
        const float4 c = C4[tid + 256 * k];
        mn = fminf(mn, fminf(fminf(c.x, c.y), fminf(c.z, c.w)));
    }
    #pragma unroll
    for (int o = 16; o; o >>= 1)
        mn = fminf(mn, __shfl_xor_sync(0xFFFFFFFFu, mn, o));
    if (l == 0) sred[w] = mn;
    __syncthreads();
    if (tid == 0) {
        float t = sred[0];
        #pragma unroll
        for (int k = 1; k < 8; k++) t = fminf(t, sred[k]);
        sred[8] = t;
        if (blockIdx.x == 0) g_Cmin = t;
    }
    __syncthreads();
    const float cmin = sred[8];

    #pragma unroll
    for (int rr = 0; rr < 4; rr++) {
        const int row = blockIdx.x * 4 + rr;
        const float val = __expf((cmin - C[(row << 8) + tid]) * INV_EPS);
        const __half hv = __float2half_rn(val);
        g_E0h[(row << 8) + tid] = hv;
        float f = __half2float(hv);
        #pragma unroll
        for (int o = 16; o; o >>= 1)
            f += __shfl_xor_sync(0xFFFFFFFFu, f, o);
        __syncthreads();
        if (l == 0) sred[w] = f;
        __syncthreads();
        if (tid == 0) {
            float s = 0.0f;
            #pragma unroll
            for (int k = 0; k < 8; k++) s += sred[k];
            g_logS[row] = __logf(s);
            g_invS[row] = 1.0f / s;
        }
    }
}

// smem layout (float offsets); E0h occupies floats [0,8192) as half[16384].
#define O_EUWT  8192    // float4[64]: (eu0, wt0, eu1, wt1)
#define O_SPART 8448    // spartA float4[384] @8448, spartB float4[384] @9984
#define O_SNU   11520   // Knu0 [256], Knu1 [256]
#define O_SEV   12032   // sev0 [256], sev1 [256]
#define O_SU    12544   // 2 x 64  (log-domain u, for du/err only)
#define O_SLM   12672   // 2 x 64  log(mu+1e-8)
#define O_SMU   12800   // 2 x 64  mu
#define O_SKMU  12928   // 2 x 64  (mu+1e-8)*e^(-cmin/eps)
#define O_SRED  13056   // 2 x 16: [8..15] du partials (16B aligned)
#define SMEM_FLOATS 13088

// err = same summation order as before: (((d0+d1)+(d2+d3))+((d4+d5)+(d6+d7)))
__device__ __forceinline__ float err_sum(const float* p) {
    const float4 a = *reinterpret_cast<const float4*>(p);
    const float4 b = *reinterpret_cast<const float4*>(p + 4);
    return ((a.x + a.y) + (a.z + a.w)) + ((b.x + b.y) + (b.z + b.w));
}

#define FFMA2(acc, a, b) \
    asm("fma.rn.f32x2 %0, %1, %2, %0;" : "+l"(acc) : "l"(a), "l"(b))
#define BCAST2(dst, s) \
    asm("mov.b64 %0, {%1, %1};" : "=l"(dst) : "f"(s))
#define UNPACK2(lo, hi, p) \
    asm("mov.b64 {%0, %1}, %2;" : "=f"(lo), "=f"(hi) : "l"(p))

// ---------------------------------------------------------------------------
// Main: multiplicative Sinkhorn, fixed shift = cmin. 2 samples/block, 512 thr,
// fp16 E0 in shared, 3 blocks/SM, PDL overlap with init.
//  - u-pass: multi-row butterfly reduce (9 shfl for 8 rows; identical tree).
//  - full v-pass: packed fma.rn.f32x2 on (av,ae) pairs.
//  - last-iteration: dead sev stores and the final barrier elided.
// ---------------------------------------------------------------------------
extern "C" __global__ void __launch_bounds__(THREADS, 3)
ot_main_kernel(const float* __restrict__ mu,
               const float* __restrict__ nu,
               float* __restrict__ out) {
    extern __shared__ float sm[];
    __half* sE0h = reinterpret_cast<__half*>(sm);

    const int tid = threadIdx.x;
    const int h   = tid >> 8;          // sample slot
    const int col = tid & 255;
    const int l   = tid & 31;
    const int w   = tid >> 5;          // 0..15
    const int ws  = w & 7;
    const int qr  = tid >> 7;          // row-quarter (v mapping)
    const int cp  = tid & 127;         // col-pair

    float* snu0   = sm + O_SNU;
    float* snu1   = sm + O_SNU + 256;
    float* sev_h  = sm + O_SEV + (h << 8);
    float* su_h   = sm + O_SU  + (h << 6);
    float* slm_h  = sm + O_SLM + (h << 6);
    float* smu_h  = sm + O_SMU + (h << 6);
    float* skmu_h = sm + O_SKMU + (h << 6);
    float* sred0  = sm + O_SRED;
    float* sred1  = sm + O_SRED + 16;
    float* sred_h = sm + O_SRED + (h << 4);
    float4* spartA = reinterpret_cast<float4*>(sm + O_SPART);
    float4* spartB = spartA + 384;

    const int s0 = blockIdx.x * 2, s1 = s0 + 1, s_h = s0 + h;

    // ---- independent prologue loads (overlap init via PDL) ----
    const float nuv = nu[s_h * N_DIM + col];
    float muv = 0.0f;
    if (col < B_DIM) muv = mu[s_h * B_DIM + col];

    cudaGridDependencySynchronize();

    const float cmin  = g_Cmin;
    const float en50  = __expf(-cmin * INV_EPS);   // e^(-cmin/eps)
    const float scale = __expf( cmin * INV_EPS);   // e^(+cmin/eps)

    // ================= PROLOGUE (one barrier) =================
    {
        const uint4* g4 = reinterpret_cast<const uint4*>(g_E0h);
        uint4* s4 = reinterpret_cast<uint4*>(sE0h);
        #pragma unroll
        for (int k = 0; k < 4; k++)
            s4[tid + THREADS * k] = g4[tid + THREADS * k];
    }
    sm[O_SNU + (h << 8) + col] = (nuv + LOG_EPS) * en50;   // Knu
    if (col < B_DIM) {
        const float mt = muv + LOG_EPS;
        const float lm = __logf(mt);
        smu_h[col]  = muv;
        slm_h[col]  = lm;
        skmu_h[col] = mt * en50;
        const float u1 = EPSV * (lm - g_logS[col]) + cmin;
        su_h[col] = u1;
        float d = fabsf(u1);
        #pragma unroll
        for (int o = 16; o; o >>= 1)
            d += __shfl_xor_sync(0xFFFFFFFFu, d, o);
        if (l == 0) sred_h[8 + ws] = d;
        const float eu = mt * g_invS[col];
        float* qp = sm + O_EUWT + (col << 2);
        qp[2 * h]     = eu;
        qp[2 * h + 1] = eu * muv;
    }
    if (l == 0 && ws >= 2) sred_h[8 + ws] = 0.0f;
    __syncthreads();                                        // P

    bool active0 = true, active1 = true;

    // ================= MAIN LOOP (v -> break -> u) =================
    for (int it = 0; it < MAX_ITER; ++it) {
        const float err0 = err_sum(sred0 + 8);
        const float err1 = err_sum(sred1 + 8);
        const bool last0 = active0 && (err0 < THRESH || it == MAX_ITER - 1);
        const bool last1 = active1 && (err1 < THRESH || it == MAX_ITER - 1);
        const bool anyLast = last0 || last1;
        const bool willEnd = (last0 || !active0) && (last1 || !active1);

        const __half2* cph = reinterpret_cast<const __half2*>(sE0h)
                           + (qr << 11) + cp;
        const float4* qw = reinterpret_cast<const float4*>(sm + O_EUWT) + (qr << 4);

        if (!anyLast) {
            // ===== LIGHT v-pass: av only =====
            float av0a = 0, av0b = 0, av1a = 0, av1b = 0;
            #pragma unroll
            for (int i = 0; i < 16; i++) {
                const float2 cf = __half22float2(cph[i << 7]);
                const float4 q  = qw[i];
                av0a = fmaf(cf.x, q.x, av0a); av0b = fmaf(cf.y, q.x, av0b);
                av1a = fmaf(cf.x, q.z, av1a); av1b = fmaf(cf.y, q.z, av1b);
            }
            if (qr) spartA[((qr - 1) << 7) + cp] = make_float4(av0a, av0b, av1a, av1b);
            __syncthreads();                                    // B4
            if (qr == 0) {
                #pragma unroll
                for (int t = 0; t < 3; t++) {
                    const float4 pa = spartA[(t << 7) + cp];
                    av0a += pa.x; av0b += pa.y; av1a += pa.z; av1b += pa.w;
                }
                const float2 kn0 = *reinterpret_cast<const float2*>(snu0 + 2 * cp);
                const float2 kn1 = *reinterpret_cast<const float2*>(snu1 + 2 * cp);
                if (active0)
                    *reinterpret_cast<float2*>(sm + O_SEV + 2 * cp)
                        = make_float2(__fdividef(kn0.x, av0a),
                                      __fdividef(kn0.y, av0b));
                if (active1)
                    *reinterpret_cast<float2*>(sm + O_SEV + 256 + 2 * cp)
                        = make_float2(__fdividef(kn1.x, av1a),
                                      __fdividef(kn1.y, av1b));
            }
            __syncthreads();                                    // B6
        } else {
            // ===== FULL v-pass: packed (av,ae) accumulators via f32x2 =====
            unsigned long long A0a = 0, A0b = 0, A1a = 0, A1b = 0;
            {
                const ulonglong2* qw2 = reinterpret_cast<const ulonglong2*>(qw);
                #pragma unroll
                for (int i = 0; i < 16; i++) {
                    const float2 cf = __half22float2(cph[i << 7]);
                    const ulonglong2 q2 = qw2[i];   // .x=(eu0,wt0) .y=(eu1,wt1)
                    unsigned long long cx, cy;
                    BCAST2(cx, cf.x);
                    BCAST2(cy, cf.y);
                    FFMA2(A0a, cx, q2.x);
                    FFMA2(A0b, cy, q2.x);
                    FFMA2(A1a, cx, q2.y);
                    FFMA2(A1b, cy, q2.y);
                }
            }
            float av0a, ae0a, av0b, ae0b, av1a, ae1a, av1b, ae1b;
            UNPACK2(av0a, ae0a, A0a);
            UNPACK2(av0b, ae0b, A0b);
            UNPACK2(av1a, ae1a, A1a);
            UNPACK2(av1b, ae1b, A1b);
            if (qr) {
                spartA[((qr - 1) << 7) + cp] = make_float4(av0a, ae0a, av1a, ae1a);
                spartB[((qr - 1) << 7) + cp] = make_float4(av0b, ae0b, av1b, ae1b);
            }
            __syncthreads();                                    // B4
            if (qr == 0) {
                #pragma unroll
                for (int t = 0; t < 3; t++) {
                    const float4 pa = spartA[(t << 7) + cp];
                    const float4 pb = spartB[(t << 7) + cp];
                    av0a += pa.x; ae0a += pa.y; av1a += pa.z; ae1a += pa.w;
                    av0b += pb.x; ae0b += pb.y; av1b += pb.z; ae1b += pb.w;
                }
                const float2 kn0 = *reinterpret_cast<const float2*>(snu0 + 2 * cp);
                const float2 kn1 = *reinterpret_cast<const float2*>(snu1 + 2 * cp);
                if (active0) {
                    const float e0a = __fdividef(kn0.x, av0a);
                    const float e0b = __fdividef(kn0.y, av0b);
                    if (last0) {
                        *reinterpret_cast<float2*>(out + s0 * N_DIM + 2 * cp)
                            = make_float2(scale * e0a * ae0a, scale * e0b * ae0b);
                    } else {
                        *reinterpret_cast<float2*>(sm + O_SEV + 2 * cp)
                            = make_float2(e0a, e0b);
                    }
                }
                if (active1) {
                    const float e1a = __fdividef(kn1.x, av1a);
                    const float e1b = __fdividef(kn1.y, av1b);
                    if (last1) {
                        *reinterpret_cast<float2*>(out + s1 * N_DIM + 2 * cp)
                            = make_float2(scale * e1a * ae1a, scale * e1b * ae1b);
                    } else {
                        *reinterpret_cast<float2*>(sm + O_SEV + 256 + 2 * cp)
                            = make_float2(e1a, e1b);
                    }
                }
            }
            if (!willEnd) __syncthreads();                      // B6 (elided at end)
        }

        if (last0) active0 = false;
        if (last1) active1 = false;
        if (!active0 && !active1) break;

        // ---- u-pass for it+1: dot, multi-row butterfly, inline eu/wt ----
        const bool act_h = h ? active1 : active0;
        if (act_h) {
            const float4 evA = reinterpret_cast<const float4*>(sev_h)[2 * l];
            const float4 evB = reinterpret_cast<const float4*>(sev_h)[2 * l + 1];
            float p0, p1, p2, p3, p4, p5, p6, p7;
            float* pp[8] = {&p0, &p1, &p2, &p3, &p4, &p5, &p6, &p7};
            #pragma unroll
            for (int r = 0; r < 8; ++r) {
                const int row = (ws << 3) + r;
                const int4 hv = reinterpret_cast<const int4*>(sE0h + (row << 8))[l];
                const __half2* hp = reinterpret_cast<const __half2*>(&hv);
                const float2 f0 = __half22float2(hp[0]);
                const float2 f1 = __half22float2(hp[1]);
                const float2 f2 = __half22float2(hp[2]);
                const float2 f3 = __half22float2(hp[3]);
                *pp[r] = f0.x * evA.x + f0.y * evA.y + f1.x * evA.z + f1.y * evA.w
                       + f2.x * evB.x + f2.y * evB.y + f3.x * evB.z + f3.y * evB.w;
            }
            // multi-row butterfly: same pairwise tree as per-row xor16..1.
            const bool hi16 = (l & 16), hi8 = (l & 8), hi4 = (l & 4);
            float x0 = hi16 ? p0 : p4;
            float x1 = hi16 ? p1 : p5;
            float x2 = hi16 ? p2 : p6;
            float x3 = hi16 ? p3 : p7;
            x0 = __shfl_xor_sync(0xFFFFFFFFu, x0, 16);
            x1 = __shfl_xor_sync(0xFFFFFFFFu, x1, 16);
            x2 = __shfl_xor_sync(0xFFFFFFFFu, x2, 16);
            x3 = __shfl_xor_sync(0xFFFFFFFFu, x3, 16);
            const float q0 = (hi16 ? p4 : p0) + x0;
            const float q1 = (hi16 ? p5 : p1) + x1;
            const float q2 = (hi16 ? p6 : p2) + x2;
            const float q3 = (hi16 ? p7 : p3) + x3;
            float y0 = hi8 ? q0 : q2;
            float y1 = hi8 ? q1 : q3;
            y0 = __shfl_xor_sync(0xFFFFFFFFu, y0, 8);
            y1 = __shfl_xor_sync(0xFFFFFFFFu, y1, 8);
            const float t0 = (hi8 ? q2 : q0) + y0;
            const float t1 = (hi8 ? q3 : q1) + y1;
            float z = hi4 ? t0 : t1;
            z = __shfl_xor_sync(0xFFFFFFFFu, z, 4);
            float t = (hi4 ? t1 : t0) + z;
            t += __shfl_xor_sync(0xFFFFFFFFu, t, 2);
            t += __shfl_xor_sync(0xFFFFFFFFu, t, 1);
            // lane l holds rowsum of row ws*8 + ((l>>2)&7)
            float myDu = 0.0f;
            if ((l & 3) == 0) {
                const int row = (ws << 3) + ((l >> 2) & 7);
                const float unew = EPSV * (slm_h[row] - __logf(t));
                myDu = fabsf(unew - su_h[row]);
                su_h[row] = unew;
                const float eu = __fdividef(skmu_h[row], t);
                *reinterpret_cast<float2*>(sm + O_EUWT + (row << 2) + 2 * h)
                    = make_float2(eu, eu * smu_h[row]);
            }
            myDu += __shfl_xor_sync(0xFFFFFFFFu, myDu, 4);
            myDu += __shfl_xor_sync(0xFFFFFFFFu, myDu, 8);
            myDu += __shfl_xor_sync(0xFFFFFFFFu, myDu, 16);
            if (l == 0) sred_h[8 + ws] = myDu;
        }
        __syncthreads();                                        // B1
    }
}

// ---------------------------------------------------------------------------
// Launch: init normally; main with PDL.
// ---------------------------------------------------------------------------
extern "C" void kernel_launch(void* const* d_in, const int* in_sizes, int n_in,
                              void* d_out, int out_size) {
    const float* mu = nullptr;
    const float* nu = nullptr;
    const float* C  = nullptr;
    for (int i = 0; i < n_in; ++i) {
        if (in_sizes[i] == S_TOT * B_DIM)      mu = (const float*)d_in[i];
        else if (in_sizes[i] == S_TOT * N_DIM) nu = (const float*)d_in[i];
        else if (in_sizes[i] == B_DIM * N_DIM) C  = (const float*)d_in[i];
    }
    float* out = (float*)d_out;

    const int smem_bytes = SMEM_FLOATS * sizeof(float);   // ~51.1 KB, 3 blk/SM
    cudaFuncSetAttribute(ot_main_kernel,
                         cudaFuncAttributeMaxDynamicSharedMemorySize, smem_bytes);

    ot_init_kernel<<<16, 256>>>(C);

    cudaLaunchConfig_t cfg = {};
    cfg.gridDim  = dim3(S_TOT / 2, 1, 1);
    cfg.blockDim = dim3(THREADS, 1, 1);
    cfg.dynamicSmemBytes = smem_bytes;
    cfg.stream = 0;
    cudaLaunchAttribute attr[1];
    attr[0].id = cudaLaunchAttributeProgrammaticStreamSerialization;
    attr[0].val.programmaticStreamSerializationAllowed = 1;
    cfg.attrs = attr;
    cfg.numAttrs = 1;
    cudaLaunchKernelEx(&cfg, ot_main_kernel, mu, nu, out);
}